// round 9
// baseline (speedup 1.0000x reference)
#include <cuda_runtime.h>

// Problem constants (fixed by the reference).
constexpr int NN = 100000;   // nodes
constexpr int NE = 1600000;  // edges
constexpr int F1 = 64;       // layer-1 out features (== Fin)
constexpr int F2 = 32;       // layer-2 out features
constexpr int SB = (NN + 1023) / 1024; // 98 scan blocks (1024 threads)
constexpr int PB = NE / 256;           // 6250 prep blocks (128 thr x 2 edges)
constexpr int GB1 = NN / 32;           // 3125 gemm blocks in fused kernel

// Scratch (device globals — referenced ONLY inside device code; passing the
// symbol as a kernel arg from host passes the host shadow address on GB300
// ATS and silently corrupts results — R5/R6 bug).
__device__ int   g_deg[NN];
__device__ int   g_off[NN + 1];
__device__ int   g_cur[NN];
__device__ int   g_bsum[SB];
__device__ int   g_ticket;
__device__ int   g_csr_src[NE];
__device__ float g_dinv[NN];
__device__ float g_h1[(size_t)NN * F1];    // raw x@W1 (NOT dinv-scaled)
__device__ float g_hs2[(size_t)NN * F2];   // (h1@W2) * dinv[row]
__device__ int   g_is64;

// ---------------------------------------------------------------------------
// init: blocks [0,SB) zero g_deg; block SB detects int64-vs-int32 edge dtype
// (int64 LE node ids < 2^31 -> all odd 32-bit words zero) and resets ticket.
__global__ void init_k(const unsigned int* __restrict__ w) {
    if (blockIdx.x == SB) {
        __shared__ int cnt;
        if (threadIdx.x == 0) cnt = 0;
        __syncthreads();
        if (w[threadIdx.x * 2 + 1] != 0u) atomicAdd(&cnt, 1);
        __syncthreads();
        if (threadIdx.x == 0) {
            g_is64 = (cnt == 0) ? 1 : 0;
            g_ticket = 0;
        }
        return;
    }
    int i = blockIdx.x * 1024 + threadIdx.x;
    if (i < NN) g_deg[i] = 0;
}

// ---------------------------------------------------------------------------
// FUSED: blocks [0, PB) -> edge-degree histogram (launch FIRST: they feed the
// critical path); blocks [PB, PB+GB1) -> raw gemm1 (h1 = x @ W1), which only
// needs to finish before agg1 and is shadowed by the CSR build.
__global__ void fused_prep_gemm1(const float* __restrict__ x,
                                 const float* __restrict__ W,
                                 const int* __restrict__ w) {
    constexpr int K = 64, ROWS = 32, XP = K + 4, FOUT = F1;
    constexpr int NT = 128;
    __shared__ float xs[ROWS][XP];
    __shared__ float ws[K][FOUT];

    int tid = threadIdx.x;
    if (blockIdx.x < PB) {
        // ---- prep phase: degree histogram, 2 edges per thread ----
        int base = blockIdx.x * 256;
        int is64 = g_is64;
#pragma unroll
        for (int r = 0; r < 2; r++) {
            int e = base + r * 128 + tid;
            int d = is64 ? w[2 * (NE + e)] : w[NE + e];
            atomicAdd(&g_deg[d], 1);
        }
        return;
    }

    // ---- gemm phase: 32 rows, 4x4 micro-tile, raw (unscaled) output ----
    int row0 = (blockIdx.x - PB) * ROWS;
    for (int f4 = tid; f4 < ROWS * K / 4; f4 += NT) {
        int r = f4 >> 4, kc = f4 & 15;
        float4 v = ((const float4*)(x + (size_t)(row0 + r) * K))[kc];
        *(float4*)&xs[r][kc * 4] = v;
    }
    for (int f4 = tid; f4 < K * FOUT / 4; f4 += NT)
        ((float4*)ws)[f4] = ((const float4*)W)[f4];
    __syncthreads();

    int j = tid % 16;
    int i = tid / 16;
    float acc[4][4] = {};
#pragma unroll 8
    for (int k = 0; k < K; k++) {
        float av[4];
#pragma unroll
        for (int r = 0; r < 4; r++) av[r] = xs[i * 4 + r][k];
        float4 b = *(const float4*)&ws[k][j * 4];
#pragma unroll
        for (int r = 0; r < 4; r++) {
            acc[r][0] = fmaf(av[r], b.x, acc[r][0]);
            acc[r][1] = fmaf(av[r], b.y, acc[r][1]);
            acc[r][2] = fmaf(av[r], b.z, acc[r][2]);
            acc[r][3] = fmaf(av[r], b.w, acc[r][3]);
        }
    }
#pragma unroll
    for (int r = 0; r < 4; r++) {
        int row = row0 + i * 4 + r;
        float4 o = make_float4(acc[r][0], acc[r][1], acc[r][2], acc[r][3]);
        *(float4*)&g_h1[(size_t)row * FOUT + j * 4] = o;
    }
}

// ---------------------------------------------------------------------------
// scan1: per-block reduce of g_deg (1024/block); LAST block (atomic ticket)
// exclusive-scans the 98 block sums in place. Deterministic.
__global__ void scan1() {
    int i = blockIdx.x * 1024 + threadIdx.x;
    int v = (i < NN) ? g_deg[i] : 0;
    int lane = threadIdx.x & 31, wid = threadIdx.x >> 5;
#pragma unroll
    for (int o = 16; o > 0; o >>= 1) v += __shfl_down_sync(0xffffffffu, v, o);
    __shared__ int ws[32];
    if (lane == 0) ws[wid] = v;
    __syncthreads();
    if (wid == 0) {
        int s = ws[lane];
#pragma unroll
        for (int o = 16; o > 0; o >>= 1) s += __shfl_down_sync(0xffffffffu, s, o);
        if (lane == 0) {
            g_bsum[blockIdx.x] = s;
            __threadfence();
            int t = atomicAdd(&g_ticket, 1);
            if (t == SB - 1) {  // last block: scan the block sums
                int r = 0;
#pragma unroll 7
                for (int k = 0; k < SB; k++) {
                    int x = g_bsum[k];
                    g_bsum[k] = r;
                    r += x;
                }
            }
        }
    }
}

// scan2: block-wide exclusive scan (1024 threads) + bsum offset; writes
// g_off, g_cur, and g_dinv (= rsqrt(deg+2), improved self-loops).
__global__ void scan2() {
    int i = blockIdx.x * 1024 + threadIdx.x;
    int v = (i < NN) ? g_deg[i] : 0;
    int lane = threadIdx.x & 31, wid = threadIdx.x >> 5;
    int x = v;
#pragma unroll
    for (int o = 1; o < 32; o <<= 1) {
        int y = __shfl_up_sync(0xffffffffu, x, o);
        if (lane >= o) x += y;
    }
    __shared__ int ws[32];
    if (lane == 31) ws[wid] = x;
    __syncthreads();
    if (wid == 0) {
        int y = ws[lane];
        int s = y;
#pragma unroll
        for (int o = 1; o < 32; o <<= 1) {
            int z = __shfl_up_sync(0xffffffffu, s, o);
            if (lane >= o) s += z;
        }
        ws[lane] = s - y;  // exclusive
    }
    __syncthreads();
    int off = g_bsum[blockIdx.x] + ws[wid] + (x - v);
    if (i < NN) {
        g_off[i] = off;
        g_cur[i] = off;
        g_dinv[i] = rsqrtf((float)v + 2.0f);
        if (i == NN - 1) g_off[NN] = off + v;
    }
}

// Reads the raw edge list (dtype-aware) — no staged src/dst arrays.
__global__ void fill_csr(const int* __restrict__ w) {
    int e = blockIdx.x * blockDim.x + threadIdx.x;
    if (e >= NE) return;
    int s, d;
    if (g_is64) {
        s = w[2 * e];
        d = w[2 * (NE + e)];
    } else {
        s = w[e];
        d = w[NE + e];
    }
    int pos = atomicAdd(&g_cur[d], 1);
    g_csr_src[pos] = s;
}

// ---------------------------------------------------------------------------
// GEMM layer 2: g_hs2[row,:] = (x[row,:] @ W) * dinv[row].  K=64, FOUT=32.
__global__ void gemm2_scale(const float* __restrict__ x,
                            const float* __restrict__ W) {
    constexpr int K = 64, ROWS = 32, XP = K + 4, FOUT = F2;
    constexpr int TJ = FOUT / 4;          // 8
    constexpr int NT = (ROWS / 4) * TJ;   // 64 threads
    __shared__ float xs[ROWS][XP];
    __shared__ float ws[K][FOUT];

    int tid = threadIdx.x;
    int row0 = blockIdx.x * ROWS;

    for (int f4 = tid; f4 < ROWS * K / 4; f4 += NT) {
        int r = f4 >> 4, kc = f4 & 15;
        float4 v = ((const float4*)(x + (size_t)(row0 + r) * K))[kc];
        *(float4*)&xs[r][kc * 4] = v;
    }
    for (int f4 = tid; f4 < K * FOUT / 4; f4 += NT)
        ((float4*)ws)[f4] = ((const float4*)W)[f4];
    __syncthreads();

    int j = tid % TJ;
    int i = tid / TJ;
    float acc[4][4] = {};
#pragma unroll 8
    for (int k = 0; k < K; k++) {
        float av[4];
#pragma unroll
        for (int r = 0; r < 4; r++) av[r] = xs[i * 4 + r][k];
        float4 b = *(const float4*)&ws[k][j * 4];
#pragma unroll
        for (int r = 0; r < 4; r++) {
            acc[r][0] = fmaf(av[r], b.x, acc[r][0]);
            acc[r][1] = fmaf(av[r], b.y, acc[r][1]);
            acc[r][2] = fmaf(av[r], b.z, acc[r][2]);
            acc[r][3] = fmaf(av[r], b.w, acc[r][3]);
        }
    }
#pragma unroll
    for (int r = 0; r < 4; r++) {
        int row = row0 + i * 4 + r;
        float dv = g_dinv[row];
        float4 o = make_float4(acc[r][0] * dv, acc[r][1] * dv,
                               acc[r][2] * dv, acc[r][3] * dv);
        *(float4*)&g_hs2[(size_t)row * FOUT + j * 4] = o;
    }
}

// ---------------------------------------------------------------------------
// Pull aggregation layer 1: one warp per dst node, fused epilogue.
// h1 is RAW: a = sum dinv[s]*h1[s]; out = relu(dv*(a + 2*dv*h_self) + b).
__global__ void agg1(const float* __restrict__ b, float* __restrict__ feat) {
    int warp = (blockIdx.x * 256 + threadIdx.x) >> 5;
    int lane = threadIdx.x & 31;
    if (warp >= NN) return;
    int beg = g_off[warp], end = g_off[warp + 1];
    const float2* __restrict__ hs = (const float2*)g_h1;
    float ax = 0.f, ay = 0.f;
    int i = beg;
    for (; i + 4 <= end; i += 4) {
        int s0 = g_csr_src[i], s1 = g_csr_src[i + 1];
        int s2 = g_csr_src[i + 2], s3 = g_csr_src[i + 3];
        float d0 = g_dinv[s0], d1 = g_dinv[s1];
        float d2 = g_dinv[s2], d3 = g_dinv[s3];
        float2 v0 = hs[s0 * 32 + lane];
        float2 v1 = hs[s1 * 32 + lane];
        float2 v2 = hs[s2 * 32 + lane];
        float2 v3 = hs[s3 * 32 + lane];
        ax = fmaf(d0, v0.x, ax); ay = fmaf(d0, v0.y, ay);
        ax = fmaf(d1, v1.x, ax); ay = fmaf(d1, v1.y, ay);
        ax = fmaf(d2, v2.x, ax); ay = fmaf(d2, v2.y, ay);
        ax = fmaf(d3, v3.x, ax); ay = fmaf(d3, v3.y, ay);
    }
    for (; i < end; i++) {
        int s = g_csr_src[i];
        float d = g_dinv[s];
        float2 v = hs[s * 32 + lane];
        ax = fmaf(d, v.x, ax);
        ay = fmaf(d, v.y, ay);
    }
    float dv = g_dinv[warp];
    float2 h = hs[warp * 32 + lane];
    float2 bb = ((const float2*)b)[lane];
    float tdv = 2.f * dv;
    float2 o;
    o.x = fmaxf(fmaf(dv, fmaf(tdv, h.x, ax), bb.x), 0.f);
    o.y = fmaxf(fmaf(dv, fmaf(tdv, h.y, ay), bb.y), 0.f);
    ((float2*)feat)[warp * 32 + lane] = o;
}

// Layer 2: g_hs2 pre-scaled by dinv[row]; each lane owns one float of the row.
__global__ void agg2(const float* __restrict__ b, float* __restrict__ out) {
    int warp = (blockIdx.x * 256 + threadIdx.x) >> 5;
    int lane = threadIdx.x & 31;
    if (warp >= NN) return;
    int beg = g_off[warp], end = g_off[warp + 1];
    const float* __restrict__ hs = g_hs2;
    float a = 0.f;
    int i = beg;
    for (; i + 4 <= end; i += 4) {
        int s0 = g_csr_src[i], s1 = g_csr_src[i + 1];
        int s2 = g_csr_src[i + 2], s3 = g_csr_src[i + 3];
        float v0 = hs[s0 * 32 + lane];
        float v1 = hs[s1 * 32 + lane];
        float v2 = hs[s2 * 32 + lane];
        float v3 = hs[s3 * 32 + lane];
        a += (v0 + v1) + (v2 + v3);
    }
    for (; i < end; i++) a += hs[g_csr_src[i] * 32 + lane];
    float dv = g_dinv[warp];
    float h = hs[warp * 32 + lane];
    out[warp * 32 + lane] = fmaf(dv, fmaf(2.f, h, a), b[lane]);
}

// ---------------------------------------------------------------------------
extern "C" void kernel_launch(void* const* d_in, const int* in_sizes, int n_in,
                              void* d_out, int out_size) {
    const float* x  = (const float*)d_in[0];
    const int*   ei = (const int*)d_in[1];
    const float* W1 = (const float*)d_in[2];
    const float* b1 = (const float*)d_in[3];
    const float* W2 = (const float*)d_in[4];
    const float* b2 = (const float*)d_in[5];

    float* out  = (float*)d_out;              // [N, 32]
    float* feat = out + (size_t)NN * F2;      // [N, 64] feature_map

    init_k<<<SB + 1, 1024>>>((const unsigned int*)ei);

    // Edge histogram (critical path, launches first) + raw gemm1 (shadowed).
    fused_prep_gemm1<<<PB + GB1, 128>>>(x, W1, ei);

    // CSR offsets (2-kernel scan; dinv fused into scan2).
    scan1<<<SB, 1024>>>();
    scan2<<<SB, 1024>>>();
    fill_csr<<<(NE + 255) / 256, 256>>>(ei);

    // Layer 1 aggregation (dinv[src]-weighted gather over raw h1).
    agg1<<<(NN * 32 + 255) / 256, 256>>>(b1, feat);

    // Layer 2 (reads h1 activations from the feature_map output region).
    gemm2_scale<<<NN / 32, 64>>>(feat, W2);
    agg2<<<(NN * 32 + 255) / 256, 256>>>(b2, out);
}